// round 12
// baseline (speedup 1.0000x reference)
#include <cuda_runtime.h>
#include <cuda_fp16.h>
#include <math.h>
#include <stdint.h>

#define NN    50000
#define NNPAD 50048   // 391 * 128
#define NTILE 391
#define NE    300000
#define NDIM  11
#define EDIM  5
#define HID   256
#define NG    1024
#define NL    4
#define BN_EPS 1e-5f
#define PGRID 148

// ---------------- scratch (device globals: allocation-free) ----------------
__device__ __half g_hh [NN*HID];       // h state (fp16 only)
__device__ __half g_z2h[NN*HID];       // pre-BN MLP output (fp16)
__device__ __half g_wf [8*HID*HID];    // weights, fp16 fragment order
__device__ float  g_sattr[NE*EDIM];    // edge attr sorted into CSR order
__device__ int    g_deg[NN];
__device__ int    g_offs[NN+1];
__device__ int    g_cursor[NN];
__device__ int    g_ssrc[NE];
__device__ float  g_bnsumL[NL*2*HID];
__device__ float  g_psum[NG*HID];
__device__ float  g_pmax[NG*HID];
__device__ int    g_cnt[NG];
__device__ float  g_gfeat[NG*3*HID];
__device__ float  g_h1[NG*HID];
__device__ float  g_h2[NG*(HID/2)];
__device__ int          g_barcnt = 0;
__device__ volatile int g_sense  = 0;

// ---------------- helpers ----------------
__device__ __forceinline__ unsigned pack2(float a, float b) {
    __half2 h = __floats2half2_rn(a, b);
    return *reinterpret_cast<unsigned*>(&h);
}
__device__ __forceinline__ float2 unpack2(unsigned u) {
    __half2 h = *reinterpret_cast<__half2*>(&u);
    return __half22float2(h);
}
__device__ __forceinline__ void cp16(void* s, const void* g) {
    unsigned sa = (unsigned)__cvta_generic_to_shared(s);
    asm volatile("cp.async.ca.shared.global [%0], [%1], 16;\n" :: "r"(sa), "l"(g));
}
__device__ __forceinline__ void gbar(int* local_sense) {
    __syncthreads();
    if (threadIdx.x == 0) {
        int s = 1 - *local_sense;
        __threadfence();
        if (atomicAdd(&g_barcnt, 1) == PGRID - 1) {
            g_barcnt = 0;
            __threadfence();
            g_sense = s;
        } else {
            while (g_sense != s) __nanosleep(64);
        }
        *local_sense = s;
    }
    __syncthreads();
}

// ---------------- init / CSR build ----------------
__global__ void k_zero_init() {
    int i = blockIdx.x * blockDim.x + threadIdx.x;
    int stride = gridDim.x * blockDim.x;
    for (int j = i; j < NN; j += stride) g_deg[j] = 0;
    for (int j = i; j < NG*HID; j += stride) { g_psum[j] = 0.f; g_pmax[j] = 0.f; }
    for (int j = i; j < NG; j += stride) g_cnt[j] = 0;
    for (int j = i; j < NL*2*HID; j += stride) g_bnsumL[j] = 0.f;
}

__global__ void k_hist(const int* __restrict__ ei) {
    int e = blockIdx.x * blockDim.x + threadIdx.x;
    if (e < NE) atomicAdd(&g_deg[ei[NE + e]], 1);
}

__global__ void k_scan() {
    __shared__ int s[1024];
    const int CH = (NN + 1023) / 1024;
    int tid = threadIdx.x;
    int start = tid * CH;
    int sum = 0;
    for (int i = 0; i < CH; i++) {
        int idx = start + i;
        if (idx < NN) sum += g_deg[idx];
    }
    s[tid] = sum;
    __syncthreads();
    for (int off = 1; off < 1024; off <<= 1) {
        int v = 0;
        if (tid >= off) v = s[tid - off];
        __syncthreads();
        if (tid >= off) s[tid] += v;
        __syncthreads();
    }
    int run = (tid == 0) ? 0 : s[tid - 1];
    for (int i = 0; i < CH; i++) {
        int idx = start + i;
        if (idx < NN) {
            g_offs[idx] = run;
            g_cursor[idx] = run;
            run += g_deg[idx];
        }
    }
    if (tid == 1023) g_offs[NN] = s[1023];
}

__global__ void k_scatter(const int* __restrict__ ei, const float* __restrict__ eattr) {
    int e = blockIdx.x * blockDim.x + threadIdx.x;
    if (e < NE) {
        int s = ei[e];
        int d = ei[NE + e];
        int pos = atomicAdd(&g_cursor[d], 1);
        g_ssrc[pos] = s;
        #pragma unroll
        for (int dd = 0; dd < EDIM; dd++)
            g_sattr[pos * EDIM + dd] = eattr[(size_t)e * EDIM + dd];
    }
}

// ---------------- weight prep: fp16 fragment order ----------------
__global__ void k_wprep(const float* __restrict__ W1, const float* __restrict__ W2) {
    int mat = blockIdx.x;           // 0..7 = layer*2 + (0:W1, 1:W2)
    int l = mat >> 1;
    const float* W = (mat & 1) ? (W2 + l * HID * HID) : (W1 + l * HID * HID);
    uint2* F = (uint2*)(g_wf + (size_t)mat * HID * HID);
    int n = threadIdx.x;            // 256
    int N8 = n >> 3, g = n & 7;
    for (int S = 0; S < 16; S++) {
        #pragma unroll
        for (int t = 0; t < 4; t++) {
            int k0 = S * 16 + 2 * t;
            float w0 = W[(k0    ) * HID + n];
            float w1 = W[(k0 + 1) * HID + n];
            float w8 = W[(k0 + 8) * HID + n];
            float w9 = W[(k0 + 9) * HID + n];
            F[(N8 * 16 + S) * 32 + g * 4 + t] = make_uint2(pack2(w0, w1), pack2(w8, w9));
        }
    }
}

// ---------------- node encoder ----------------
__global__ void k_enc(const float* __restrict__ x, const float* __restrict__ W,
                      const float* __restrict__ b) {
    __shared__ float sx[NDIM];
    int node = blockIdx.x;
    int c = threadIdx.x;
    if (c < NDIM) sx[c] = x[node * NDIM + c];
    __syncthreads();
    float a = b[c];
    #pragma unroll
    for (int k = 0; k < NDIM; k++) a += sx[k] * W[k * HID + c];
    g_hh[(size_t)node * HID + c] = __float2half(fmaxf(a, 0.f));
}

// ---------------- persistent network: 4x (aggregate + MLP + BN) ----------------
// grid = 148 CTAs x 512 threads, all resident (1 CTA/SM, 170KB smem).
// smem: sWt 8KB @0, A 64KB @8192, B 2x16KB @73728, z1 64KB @106496,
//       bnScale 1KB @172032, bnShift 1KB @173056  => 174080 total.
#define NET_SMEM 174080
__global__ void __launch_bounds__(512, 1)
k_net(const float* __restrict__ edgeW_all, const float* __restrict__ edgeb_all,
      const float* __restrict__ b1_all, const float* __restrict__ b2_all,
      const float* __restrict__ bng, const float* __restrict__ bnb) {
    extern __shared__ char sm[];
    float* sWt = (float*)sm;                    // EDIM*256 floats
    uint2* smA = (uint2*)(sm + 8192);           // A frags (64KB)
    char*  smB = sm + 73728;                    // 2 x 16KB
    uint2* smZ = (uint2*)(sm + 106496);         // z1 (64KB)
    float* smSc = (float*)(sm + 172032);        // 256 floats
    float* smSh = (float*)(sm + 173056);        // 256 floats

    const int tid = threadIdx.x;
    const int wid = tid >> 5, lane = tid & 31;
    const int g = lane >> 2, t = lane & 3;
    const int warpRow = wid >> 3;
    const int wc = wid & 7;
    const unsigned FULL = 0xffffffffu;
    int sense = 0;

    for (int l = 0; l < NL; l++) {
        const float* eW = edgeW_all + (size_t)l * EDIM * HID;
        const float* eb = edgeb_all + l * HID;
        const __half* W1f = g_wf + (size_t)(l * 2 + 0) * HID * HID;
        const __half* W2f = g_wf + (size_t)(l * 2 + 1) * HID * HID;
        const float* b1 = b1_all + l * HID;
        const float* b2 = b2_all + l * HID;
        float* bnsum = g_bnsumL + l * 2 * HID;

        auto load_B = [&](int buf, int st, const __half* Bf) {
            char* sB = smB + buf * 16384;
            #pragma unroll
            for (int i = 0; i < 2; i++) {
                int ch = tid + i * 512;
                int N8 = ch >> 5, rem = ch & 31;
                const char* gp = (const char*)Bf +
                    (((size_t)N8 * 16 + st * 2) * 256 + rem * 16);
                cp16(sB + ch * 16, gp);
            }
        };

        // edge weight transposed into smem
        for (int i = tid; i < EDIM * 256; i += 512) {
            int d = i >> 8, c = i & 255;
            int S = c >> 4, k = c & 15;
            int t0 = (k >> 1) & 1, bb = k & 1, grp = k >> 2;
            int j = bb + ((grp & 1) << 2) + ((grp >> 1) << 1);
            int ll = S * 2 + t0;
            sWt[d * 256 + j * 32 + ll] = eW[i];
        }
        __syncthreads();

        for (int tile = blockIdx.x; tile < NTILE; tile += PGRID) {
            const int bm = tile * 128;

            // prefetch W1 stage 0 (overlaps aggregation)
            load_B(0, 0, W1f);
            asm volatile("cp.async.commit_group;");

            // ===== stage 0: aggregation -> smem A frags =====
            {
                int S = lane >> 1, t0 = lane & 1;
                int base2 = S * 8 + t0;
                int hloc = (wid >> 3) & 1, gloc = wid & 7;

                float ebr[8];
                {
                    const float2* eb2 = (const float2*)eb;
                    float2 e0 = eb2[base2],     e1 = eb2[base2 + 4];
                    float2 e2 = eb2[base2 + 2], e3 = eb2[base2 + 6];
                    ebr[0]=e0.x; ebr[1]=e0.y; ebr[2]=e1.x; ebr[3]=e1.y;
                    ebr[4]=e2.x; ebr[5]=e2.y; ebr[6]=e3.x; ebr[7]=e3.y;
                }
                float wj[8][EDIM];
                #pragma unroll
                for (int j = 0; j < 8; j++)
                    #pragma unroll
                    for (int d = 0; d < EDIM; d++) wj[j][d] = sWt[d * 256 + j * 32 + lane];

                const unsigned* hh2 = (const unsigned*)g_hh;
                for (int i = 0; i < 8; i++) {
                    int node = bm + i * 16 + wid;
                    float rv[8] = {0,0,0,0,0,0,0,0};
                    if (node < NN) {
                        float acc[8] = {0,0,0,0,0,0,0,0};
                        int e0i = g_offs[node], e1i = g_offs[node + 1];
                        #pragma unroll 2
                        for (int e = e0i; e < e1i; e++) {
                            int src = g_ssrc[e];
                            float ea0 = g_sattr[e*EDIM+0];
                            float ea1 = g_sattr[e*EDIM+1];
                            float ea2 = g_sattr[e*EDIM+2];
                            float ea3 = g_sattr[e*EDIM+3];
                            float ea4 = g_sattr[e*EDIM+4];
                            size_t rb = (size_t)src * 128 + base2;
                            float2 h0 = unpack2(hh2[rb]);
                            float2 h1 = unpack2(hh2[rb + 4]);
                            float2 h2 = unpack2(hh2[rb + 2]);
                            float2 h3 = unpack2(hh2[rb + 6]);
                            float hr[8] = {h0.x,h0.y,h1.x,h1.y,h2.x,h2.y,h3.x,h3.y};
                            #pragma unroll
                            for (int j = 0; j < 8; j++) {
                                float m = hr[j] + ebr[j]
                                        + ea0 * wj[j][0] + ea1 * wj[j][1] + ea2 * wj[j][2]
                                        + ea3 * wj[j][3] + ea4 * wj[j][4];
                                acc[j] += fmaxf(m, 0.f);
                            }
                        }
                        size_t nb = (size_t)node * 128 + base2;
                        float2 v0 = unpack2(hh2[nb]),     v1 = unpack2(hh2[nb + 4]);
                        float2 v2 = unpack2(hh2[nb + 2]), v3 = unpack2(hh2[nb + 6]);
                        rv[0]=v0.x+acc[0]; rv[1]=v0.y+acc[1]; rv[2]=v1.x+acc[2]; rv[3]=v1.y+acc[3];
                        rv[4]=v2.x+acc[4]; rv[5]=v2.y+acc[5]; rv[6]=v3.x+acc[6]; rv[7]=v3.y+acc[7];
                    }
                    int ubase = ((i * 16 + S) * 2 + hloc) * 32;
                    smA[ubase + gloc * 4 + t0]     = make_uint2(pack2(rv[0], rv[1]), pack2(rv[2], rv[3]));
                    smA[ubase + gloc * 4 + t0 + 2] = make_uint2(pack2(rv[4], rv[5]), pack2(rv[6], rv[7]));
                }
            }
            __syncthreads();

            float acc[4][4][4];

            // ===== stage 1: z1 = relu(A@W1 + b1) =====
            #pragma unroll
            for (int i = 0; i < 4; i++)
                #pragma unroll
                for (int j = 0; j < 4; j++) {
                    acc[i][j][0]=0.f; acc[i][j][1]=0.f; acc[i][j][2]=0.f; acc[i][j][3]=0.f;
                }

            for (int st = 0; st < 8; st++) {
                int buf = st & 1;
                if (st + 1 < 8) {
                    load_B(buf ^ 1, st + 1, W1f);
                    asm volatile("cp.async.commit_group;");
                    asm volatile("cp.async.wait_group 1;");
                } else {
                    asm volatile("cp.async.wait_group 0;");
                }
                __syncthreads();
                const uint2* sB2 = (const uint2*)(smB + buf * 16384);
                #pragma unroll
                for (int Sl = 0; Sl < 2; Sl++) {
                    int S = st * 2 + Sl;
                    unsigned af[4][4];
                    unsigned bf[4][2];
                    #pragma unroll
                    for (int mt = 0; mt < 4; mt++) {
                        int mtIdx = warpRow * 4 + mt;
                        uint2 u0 = smA[((mtIdx * 16 + S) * 2 + 0) * 32 + lane];
                        uint2 u1 = smA[((mtIdx * 16 + S) * 2 + 1) * 32 + lane];
                        af[mt][0] = u0.x; af[mt][1] = u1.x; af[mt][2] = u0.y; af[mt][3] = u1.y;
                    }
                    #pragma unroll
                    for (int nt = 0; nt < 4; nt++) {
                        uint2 ub = sB2[(wc * 4 + nt) * 64 + Sl * 32 + lane];
                        bf[nt][0] = ub.x; bf[nt][1] = ub.y;
                    }
                    #pragma unroll
                    for (int mt = 0; mt < 4; mt++)
                        #pragma unroll
                        for (int nt = 0; nt < 4; nt++) {
                            asm volatile(
                                "mma.sync.aligned.m16n8k16.row.col.f32.f16.f16.f32 "
                                "{%0,%1,%2,%3}, {%4,%5,%6,%7}, {%8,%9}, {%0,%1,%2,%3};\n"
                                : "+f"(acc[mt][nt][0]), "+f"(acc[mt][nt][1]),
                                  "+f"(acc[mt][nt][2]), "+f"(acc[mt][nt][3])
                                : "r"(af[mt][0]), "r"(af[mt][1]), "r"(af[mt][2]), "r"(af[mt][3]),
                                  "r"(bf[nt][0]), "r"(bf[nt][1]));
                        }
                }
                __syncthreads();
            }

            load_B(0, 0, W2f);
            asm volatile("cp.async.commit_group;");

            // stage-1 epilogue -> z1 smem frags
            #pragma unroll
            for (int mt = 0; mt < 4; mt++) {
                int Rl = warpRow * 4 + mt;
                #pragma unroll
                for (int j = 0; j < 2; j++) {
                    int S = wc * 2 + j;
                    int ntA = 2 * j, ntB = 2 * j + 1;
                    int cA = wc * 32 + ntA * 8 + 2 * t;
                    int cB = cA + 8;
                    float bA0 = b1[cA], bA1 = b1[cA + 1];
                    float bB0 = b1[cB], bB1 = b1[cB + 1];
                    float a0 = fmaxf(acc[mt][ntA][0] + bA0, 0.f);
                    float a1 = fmaxf(acc[mt][ntA][1] + bA1, 0.f);
                    float a2 = fmaxf(acc[mt][ntA][2] + bA0, 0.f);
                    float a3 = fmaxf(acc[mt][ntA][3] + bA1, 0.f);
                    float b0v = fmaxf(acc[mt][ntB][0] + bB0, 0.f);
                    float b1v = fmaxf(acc[mt][ntB][1] + bB1, 0.f);
                    float b2v = fmaxf(acc[mt][ntB][2] + bB0, 0.f);
                    float b3v = fmaxf(acc[mt][ntB][3] + bB1, 0.f);
                    int ubase = ((Rl * 16 + S) * 2) * 32;
                    smZ[ubase + lane]      = make_uint2(pack2(a0, a1), pack2(b0v, b1v));
                    smZ[ubase + 32 + lane] = make_uint2(pack2(a2, a3), pack2(b2v, b3v));
                }
            }

            // ===== stage 2: z2 = z1 @ W2 + b2 =====
            #pragma unroll
            for (int i = 0; i < 4; i++)
                #pragma unroll
                for (int j = 0; j < 4; j++) {
                    acc[i][j][0]=0.f; acc[i][j][1]=0.f; acc[i][j][2]=0.f; acc[i][j][3]=0.f;
                }
            __syncthreads();

            for (int st = 0; st < 8; st++) {
                int buf = st & 1;
                if (st + 1 < 8) {
                    load_B(buf ^ 1, st + 1, W2f);
                    asm volatile("cp.async.commit_group;");
                    asm volatile("cp.async.wait_group 1;");
                } else {
                    asm volatile("cp.async.wait_group 0;");
                }
                __syncthreads();
                const uint2* sB2 = (const uint2*)(smB + buf * 16384);
                #pragma unroll
                for (int Sl = 0; Sl < 2; Sl++) {
                    int S = st * 2 + Sl;
                    unsigned af[4][4];
                    unsigned bf[4][2];
                    #pragma unroll
                    for (int mt = 0; mt < 4; mt++) {
                        int mtIdx = warpRow * 4 + mt;
                        uint2 u0 = smZ[((mtIdx * 16 + S) * 2 + 0) * 32 + lane];
                        uint2 u1 = smZ[((mtIdx * 16 + S) * 2 + 1) * 32 + lane];
                        af[mt][0] = u0.x; af[mt][1] = u1.x; af[mt][2] = u0.y; af[mt][3] = u1.y;
                    }
                    #pragma unroll
                    for (int nt = 0; nt < 4; nt++) {
                        uint2 ub = sB2[(wc * 4 + nt) * 64 + Sl * 32 + lane];
                        bf[nt][0] = ub.x; bf[nt][1] = ub.y;
                    }
                    #pragma unroll
                    for (int mt = 0; mt < 4; mt++)
                        #pragma unroll
                        for (int nt = 0; nt < 4; nt++) {
                            asm volatile(
                                "mma.sync.aligned.m16n8k16.row.col.f32.f16.f16.f32 "
                                "{%0,%1,%2,%3}, {%4,%5,%6,%7}, {%8,%9}, {%0,%1,%2,%3};\n"
                                : "+f"(acc[mt][nt][0]), "+f"(acc[mt][nt][1]),
                                  "+f"(acc[mt][nt][2]), "+f"(acc[mt][nt][3])
                                : "r"(af[mt][0]), "r"(af[mt][1]), "r"(af[mt][2]), "r"(af[mt][3]),
                                  "r"(bf[nt][0]), "r"(bf[nt][1]));
                        }
                }
                __syncthreads();
            }

            // stage-2 epilogue: fp16 z2 + BN sums
            unsigned* Z1 = (unsigned*)g_z2h;
            #pragma unroll
            for (int nt = 0; nt < 4; nt++) {
                int c0 = wc * 32 + nt * 8 + 2 * t;
                float b0 = b2[c0], b1v = b2[c0 + 1];
                float s0 = 0.f, q0 = 0.f, s1 = 0.f, q1 = 0.f;
                #pragma unroll
                for (int mt = 0; mt < 4; mt++) {
                    int r0 = bm + warpRow * 64 + mt * 16 + g;
                    int r1 = r0 + 8;
                    float v0 = acc[mt][nt][0] + b0;
                    float v1 = acc[mt][nt][1] + b1v;
                    float v2 = acc[mt][nt][2] + b0;
                    float v3 = acc[mt][nt][3] + b1v;
                    if (r0 < NN) {
                        Z1[((size_t)r0 * HID + c0) >> 1] = pack2(v0, v1);
                        s0 += v0; q0 += v0 * v0; s1 += v1; q1 += v1 * v1;
                    }
                    if (r1 < NN) {
                        Z1[((size_t)r1 * HID + c0) >> 1] = pack2(v2, v3);
                        s0 += v2; q0 += v2 * v2; s1 += v3; q1 += v3 * v3;
                    }
                }
                #pragma unroll
                for (int off = 16; off >= 4; off >>= 1) {
                    s0 += __shfl_down_sync(FULL, s0, off);
                    q0 += __shfl_down_sync(FULL, q0, off);
                    s1 += __shfl_down_sync(FULL, s1, off);
                    q1 += __shfl_down_sync(FULL, q1, off);
                }
                if (lane < 4) {
                    atomicAdd(&bnsum[c0],           s0);
                    atomicAdd(&bnsum[c0 + 1],       s1);
                    atomicAdd(&bnsum[HID + c0],     q0);
                    atomicAdd(&bnsum[HID + c0 + 1], q1);
                }
            }
            __syncthreads();   // smA/smZ reuse safety for next tile
        }

        // ===== all tiles done: global barrier, then BN fin + apply =====
        gbar(&sense);

        if (tid < HID) {
            float mu = bnsum[tid] * (1.f / NN);
            float var = bnsum[HID + tid] * (1.f / NN) - mu * mu;
            float inv = rsqrtf(var + BN_EPS);
            float sc = inv * bng[l * HID + tid];
            smSc[tid] = sc;
            smSh[tid] = bnb[l * HID + tid] - mu * sc;
        }
        __syncthreads();

        // bn_apply slice (4-channel units)
        for (int idx = blockIdx.x * 512 + tid; idx < NN * 64; idx += PGRID * 512) {
            int c4 = idx & 63;
            uint2 zu = ((const uint2*)g_z2h)[idx];
            float2 z01 = unpack2(zu.x);
            float2 z23 = unpack2(zu.y);
            float4 sc = ((const float4*)smSc)[c4];
            float4 sh = ((const float4*)smSh)[c4];
            uint2 hu = ((const uint2*)g_hh)[idx];
            float2 h01 = unpack2(hu.x);
            float2 h23 = unpack2(hu.y);
            float r0 = fmaxf(z01.x * sc.x + sh.x, 0.f) + h01.x;
            float r1 = fmaxf(z01.y * sc.y + sh.y, 0.f) + h01.y;
            float r2 = fmaxf(z23.x * sc.z + sh.z, 0.f) + h23.x;
            float r3 = fmaxf(z23.y * sc.w + sh.w, 0.f) + h23.y;
            ((uint2*)g_hh)[idx] = make_uint2(pack2(r0, r1), pack2(r2, r3));
        }
        gbar(&sense);
    }
}

// ---------------- fp32 SIMT GEMM (head only) ----------------
template <int RELU>
__global__ void k_gemm(const float* __restrict__ A, const float* __restrict__ B,
                       const float* __restrict__ bias, float* __restrict__ C,
                       int M, int N, int K) {
    __shared__ float As[16][64];
    __shared__ float Bs[16][64];
    int tid = threadIdx.x;
    int tx = tid & 15, ty = tid >> 4;
    int bm = blockIdx.x * 64, bn = blockIdx.y * 64;
    int aR = tid >> 2;
    int aC = (tid & 3) * 4;
    int bR = tid >> 4;
    int bC = (tid & 15) * 4;
    int gArow = bm + aR;
    float acc[4][4] = {};
    for (int k0 = 0; k0 < K; k0 += 16) {
        float4 av = (gArow < M) ? *(const float4*)(A + (size_t)gArow * K + k0 + aC)
                                : make_float4(0.f, 0.f, 0.f, 0.f);
        As[aC + 0][aR] = av.x;
        As[aC + 1][aR] = av.y;
        As[aC + 2][aR] = av.z;
        As[aC + 3][aR] = av.w;
        *(float4*)&Bs[bR][bC] = *(const float4*)(B + (size_t)(k0 + bR) * N + bn + bC);
        __syncthreads();
        #pragma unroll
        for (int k = 0; k < 16; k++) {
            float4 a4 = *(const float4*)&As[k][ty * 4];
            float4 b4 = *(const float4*)&Bs[k][tx * 4];
            float ar[4] = {a4.x, a4.y, a4.z, a4.w};
            float br[4] = {b4.x, b4.y, b4.z, b4.w};
            #pragma unroll
            for (int i = 0; i < 4; i++)
                #pragma unroll
                for (int j = 0; j < 4; j++)
                    acc[i][j] += ar[i] * br[j];
        }
        __syncthreads();
    }
    #pragma unroll
    for (int i = 0; i < 4; i++) {
        int r = bm + ty * 4 + i;
        if (r < M) {
            #pragma unroll
            for (int j = 0; j < 4; j++) {
                int c = bn + tx * 4 + j;
                float v = acc[i][j] + bias[c];
                if (RELU) v = fmaxf(v, 0.f);
                C[(size_t)r * N + c] = v;
            }
        }
    }
}

// ---------------- pooling ----------------
__global__ void k_pool(const int* __restrict__ batch) {
    __shared__ int sb[128];
    int c = threadIdx.x;
    int n0 = blockIdx.x * 128;
    int n1 = min(n0 + 128, NN);
    if (c < 128 && n0 + c < NN) sb[c] = batch[n0 + c];
    __syncthreads();
    float accS = 0.f, accM = 0.f;
    int cur = sb[0];
    int cnt = 0;
    for (int n = n0; n < n1; n++) {
        int gg = sb[n - n0];
        if (gg != cur) {
            atomicAdd(&g_psum[cur * HID + c], accS);
            atomicMax((int*)&g_pmax[cur * HID + c], __float_as_int(accM));
            if (c == 0) atomicAdd(&g_cnt[cur], cnt);
            accS = 0.f; accM = 0.f; cnt = 0; cur = gg;
        }
        float v = __half2float(g_hh[(size_t)n * HID + c]);
        accS += v;
        accM = fmaxf(accM, v);
        cnt++;
    }
    atomicAdd(&g_psum[cur * HID + c], accS);
    atomicMax((int*)&g_pmax[cur * HID + c], __float_as_int(accM));
    if (c == 0) atomicAdd(&g_cnt[cur], cnt);
}

__global__ void k_pool_fin() {
    int g = blockIdx.x, c = threadIdx.x;
    float s = g_psum[g * HID + c];
    float cnt = (float)max(g_cnt[g], 1);
    g_gfeat[g * 3 * HID + c]            = s / cnt;
    g_gfeat[g * 3 * HID + HID + c]      = s;
    g_gfeat[g * 3 * HID + 2 * HID + c]  = g_pmax[g * HID + c];
}

// ---------------- head final ----------------
__global__ void k_final(const float* __restrict__ W3, const float* __restrict__ b3,
                        float* __restrict__ out) {
    __shared__ float red[128];
    int g = blockIdx.x, t = threadIdx.x;
    red[t] = g_h2[g * 128 + t] * W3[t];
    __syncthreads();
    for (int off = 64; off > 0; off >>= 1) {
        if (t < off) red[t] += red[t + off];
        __syncthreads();
    }
    if (t == 0) out[g] = red[0] + b3[0];
}

// ---------------- launch ----------------
extern "C" void kernel_launch(void* const* d_in, const int* in_sizes, int n_in,
                              void* d_out, int out_size) {
    const float* x     = (const float*)d_in[0];
    const int*   ei    = (const int*)  d_in[1];
    const float* eattr = (const float*)d_in[2];
    const int*   batch = (const int*)  d_in[3];
    const float* encW  = (const float*)d_in[4];
    const float* encb  = (const float*)d_in[5];
    const float* edgeW = (const float*)d_in[6];
    const float* edgeb = (const float*)d_in[7];
    const float* W1    = (const float*)d_in[8];
    const float* b1    = (const float*)d_in[9];
    const float* W2    = (const float*)d_in[10];
    const float* b2    = (const float*)d_in[11];
    const float* bng   = (const float*)d_in[12];
    const float* bnb   = (const float*)d_in[13];
    const float* hW1   = (const float*)d_in[14];
    const float* hb1   = (const float*)d_in[15];
    const float* hW2   = (const float*)d_in[16];
    const float* hb2   = (const float*)d_in[17];
    const float* hW3   = (const float*)d_in[18];
    const float* hb3   = (const float*)d_in[19];
    float* out = (float*)d_out;

    float *p_gf, *p_h1, *p_h2;
    cudaGetSymbolAddress((void**)&p_gf, g_gfeat);
    cudaGetSymbolAddress((void**)&p_h1, g_h1);
    cudaGetSymbolAddress((void**)&p_h2, g_h2);

    cudaFuncSetAttribute(k_net, cudaFuncAttributeMaxDynamicSharedMemorySize, NET_SMEM);

    // CSR build + init + weight prep
    k_zero_init<<<512, 256>>>();
    k_hist<<<(NE + 255) / 256, 256>>>(ei);
    k_scan<<<1, 1024>>>();
    k_scatter<<<(NE + 255) / 256, 256>>>(ei, eattr);
    k_wprep<<<8, 256>>>(W1, W2);

    // encoder
    k_enc<<<NN, HID>>>(x, encW, encb);

    // persistent 4-layer network
    k_net<<<PGRID, 512, NET_SMEM>>>(edgeW, edgeb, b1, b2, bng, bnb);

    // pooling + head
    k_pool<<<(NN + 127) / 128, 256>>>(batch);
    k_pool_fin<<<NG, HID>>>();
    k_gemm<1><<<dim3(NG / 64, HID / 64), 256>>>(p_gf, hW1, hb1, p_h1, NG, HID, 3 * HID);
    k_gemm<1><<<dim3(NG / 64, (HID / 2) / 64), 256>>>(p_h1, hW2, hb2, p_h2, NG, HID / 2, HID);
    k_final<<<NG, 128>>>(hW3, hb3, out);
}

// round 17
// speedup vs baseline: 1.0801x; 1.0801x over previous
#include <cuda_runtime.h>
#include <cuda_fp16.h>
#include <math.h>
#include <stdint.h>

#define NN    50000
#define NNPAD 50048   // 391 * 128
#define NE    300000
#define NDIM  11
#define EDIM  5
#define HID   256
#define NG    1024
#define NL    4
#define BN_EPS 1e-5f

// ---------------- scratch (device globals: allocation-free) ----------------
__device__ __half g_hh [NN*HID];       // h state (fp16 only)
__device__ __half g_z2h[NN*HID];       // pre-BN MLP output (fp16)
__device__ __half g_wf [8*HID*HID];    // weights, fp16 fragment order
__device__ float  g_sattr[NE*EDIM];    // edge attr sorted into CSR order
__device__ int    g_deg[NN];
__device__ int    g_offs[NN+1];
__device__ int    g_cursor[NN];
__device__ int    g_ssrc[NE];
__device__ float  g_bnsumL[NL*2*HID];  // per-layer slots, zeroed once
__device__ float  g_psum[NG*HID];
__device__ float  g_pmax[NG*HID];
__device__ int    g_cnt[NG];
__device__ float  g_gfeat[NG*3*HID];
__device__ float  g_h1[NG*HID];
__device__ float  g_h2[NG*(HID/2)];

// ---------------- helpers ----------------
__device__ __forceinline__ unsigned pack2(float a, float b) {
    __half2 h = __floats2half2_rn(a, b);
    return *reinterpret_cast<unsigned*>(&h);
}
__device__ __forceinline__ float2 unpack2(unsigned u) {
    __half2 h = *reinterpret_cast<__half2*>(&u);
    return __half22float2(h);
}
__device__ __forceinline__ void cp16(void* s, const void* g) {
    unsigned sa = (unsigned)__cvta_generic_to_shared(s);
    asm volatile("cp.async.ca.shared.global [%0], [%1], 16;\n" :: "r"(sa), "l"(g));
}

// ---------------- init / CSR build ----------------
__global__ void k_zero_init() {
    int i = blockIdx.x * blockDim.x + threadIdx.x;
    int stride = gridDim.x * blockDim.x;
    for (int j = i; j < NN; j += stride) g_deg[j] = 0;
    for (int j = i; j < NG*HID; j += stride) { g_psum[j] = 0.f; g_pmax[j] = 0.f; }
    for (int j = i; j < NG; j += stride) g_cnt[j] = 0;
    for (int j = i; j < NL*2*HID; j += stride) g_bnsumL[j] = 0.f;
}

__global__ void k_hist(const int* __restrict__ ei) {
    int e = blockIdx.x * blockDim.x + threadIdx.x;
    if (e < NE) atomicAdd(&g_deg[ei[NE + e]], 1);
}

__global__ void k_scan() {
    __shared__ int s[1024];
    const int CH = (NN + 1023) / 1024;
    int tid = threadIdx.x;
    int start = tid * CH;
    int sum = 0;
    for (int i = 0; i < CH; i++) {
        int idx = start + i;
        if (idx < NN) sum += g_deg[idx];
    }
    s[tid] = sum;
    __syncthreads();
    for (int off = 1; off < 1024; off <<= 1) {
        int v = 0;
        if (tid >= off) v = s[tid - off];
        __syncthreads();
        if (tid >= off) s[tid] += v;
        __syncthreads();
    }
    int run = (tid == 0) ? 0 : s[tid - 1];
    for (int i = 0; i < CH; i++) {
        int idx = start + i;
        if (idx < NN) {
            g_offs[idx] = run;
            g_cursor[idx] = run;
            run += g_deg[idx];
        }
    }
    if (tid == 1023) g_offs[NN] = s[1023];
}

__global__ void k_scatter(const int* __restrict__ ei, const float* __restrict__ eattr) {
    int e = blockIdx.x * blockDim.x + threadIdx.x;
    if (e < NE) {
        int s = ei[e];
        int d = ei[NE + e];
        int pos = atomicAdd(&g_cursor[d], 1);
        g_ssrc[pos] = s;
        #pragma unroll
        for (int dd = 0; dd < EDIM; dd++)
            g_sattr[pos * EDIM + dd] = eattr[(size_t)e * EDIM + dd];
    }
}

// ---------------- weight prep: fp16 fragment order ----------------
__global__ void k_wprep(const float* __restrict__ W1, const float* __restrict__ W2) {
    int mat = blockIdx.x;           // 0..7 = layer*2 + (0:W1, 1:W2)
    int l = mat >> 1;
    const float* W = (mat & 1) ? (W2 + l * HID * HID) : (W1 + l * HID * HID);
    uint2* F = (uint2*)(g_wf + (size_t)mat * HID * HID);
    int n = threadIdx.x;            // 256
    int N8 = n >> 3, g = n & 7;
    for (int S = 0; S < 16; S++) {
        #pragma unroll
        for (int t = 0; t < 4; t++) {
            int k0 = S * 16 + 2 * t;
            float w0 = W[(k0    ) * HID + n];
            float w1 = W[(k0 + 1) * HID + n];
            float w8 = W[(k0 + 8) * HID + n];
            float w9 = W[(k0 + 9) * HID + n];
            F[(N8 * 16 + S) * 32 + g * 4 + t] = make_uint2(pack2(w0, w1), pack2(w8, w9));
        }
    }
}

// ---------------- node encoder ----------------
__global__ void k_enc(const float* __restrict__ x, const float* __restrict__ W,
                      const float* __restrict__ b) {
    __shared__ float sx[NDIM];
    int node = blockIdx.x;
    int c = threadIdx.x;
    if (c < NDIM) sx[c] = x[node * NDIM + c];
    __syncthreads();
    float a = b[c];
    #pragma unroll
    for (int k = 0; k < NDIM; k++) a += sx[k] * W[k * HID + c];
    g_hh[(size_t)node * HID + c] = __float2half(fmaxf(a, 0.f));
}

// ---------------- fused GINE layer: aggregate + MLP + BN stats ----------------
// 512 threads / 16 warps. Block = 128 nodes x full 256 channels.
// smem: sWt 8KB @0, A 64KB @8192, B 2x16KB @73728, z1 64KB @106496 => 168KB, 1 CTA/SM.
#define LYR_SMEM 172032
__global__ void __launch_bounds__(512, 1)
k_layer(const float* __restrict__ eW, const float* __restrict__ eb,
        const __half* __restrict__ W1f, const __half* __restrict__ W2f,
        const float* __restrict__ b1, const float* __restrict__ b2,
        __half* __restrict__ Zh, float* __restrict__ bnsum) {
    extern __shared__ char sm[];
    float* sWt = (float*)sm;                    // EDIM*256 floats
    uint2* smA = (uint2*)(sm + 8192);           // resident A frags (64KB)
    char*  smB = sm + 73728;                    // 2 x 16KB
    uint2* smZ = (uint2*)(sm + 106496);         // z1 (64KB)

    const int tid = threadIdx.x;
    const int wid = tid >> 5, lane = tid & 31;
    const int g = lane >> 2, t = lane & 3;
    const int warpRow = wid >> 3;      // 0..1 (64 rows) -- MLP role
    const int wc = wid & 7;            // 0..7 (32 cols) -- MLP role
    const int bm = blockIdx.x * 128;
    const unsigned FULL = 0xffffffffu;

    auto load_B = [&](int buf, int st, const __half* Bf) {
        char* sB = smB + buf * 16384;
        #pragma unroll
        for (int i = 0; i < 2; i++) {
            int ch = tid + i * 512;       // 1024 chunks of 16B
            int N8 = ch >> 5, rem = ch & 31;
            const char* gp = (const char*)Bf +
                (((size_t)N8 * 16 + st * 2) * 256 + rem * 16);
            cp16(sB + ch * 16, gp);
        }
    };

    // edge weight transposed into smem: sWt[d][j*32 + l]
    for (int i = tid; i < EDIM * 256; i += 512) {
        int d = i >> 8, c = i & 255;
        int S = c >> 4, k = c & 15;
        int t0 = (k >> 1) & 1, bb = k & 1, grp = k >> 2;
        int j = bb + ((grp & 1) << 2) + ((grp >> 1) << 1);
        int l = S * 2 + t0;
        sWt[d * 256 + j * 32 + l] = eW[i];
    }
    // prefetch W1 stage 0 (overlaps aggregation)
    load_B(0, 0, W1f);
    asm volatile("cp.async.commit_group;");
    __syncthreads();   // sWt ready

    // ================= stage 0: aggregation -> smem A frags =================
    {
        int S = lane >> 1, t0 = lane & 1;
        int base2 = S * 8 + t0;
        int hloc = (wid >> 3) & 1, gloc = wid & 7;

        float ebr[8];
        {
            const float2* eb2 = (const float2*)eb;
            float2 e0 = eb2[base2],     e1 = eb2[base2 + 4];
            float2 e2 = eb2[base2 + 2], e3 = eb2[base2 + 6];
            ebr[0]=e0.x; ebr[1]=e0.y; ebr[2]=e1.x; ebr[3]=e1.y;
            ebr[4]=e2.x; ebr[5]=e2.y; ebr[6]=e3.x; ebr[7]=e3.y;
        }
        float wj[8][EDIM];
        #pragma unroll
        for (int j = 0; j < 8; j++)
            #pragma unroll
            for (int d = 0; d < EDIM; d++) wj[j][d] = sWt[d * 256 + j * 32 + lane];

        const unsigned* hh2 = (const unsigned*)g_hh;
        for (int i = 0; i < 8; i++) {
            int node = bm + i * 16 + wid;
            float rv[8] = {0,0,0,0,0,0,0,0};
            if (node < NN) {
                float acc[8] = {0,0,0,0,0,0,0,0};
                int e0i = g_offs[node], e1i = g_offs[node + 1];
                #pragma unroll 2
                for (int e = e0i; e < e1i; e++) {
                    int src = g_ssrc[e];
                    float ea0 = g_sattr[e*EDIM+0];
                    float ea1 = g_sattr[e*EDIM+1];
                    float ea2 = g_sattr[e*EDIM+2];
                    float ea3 = g_sattr[e*EDIM+3];
                    float ea4 = g_sattr[e*EDIM+4];
                    size_t rb = (size_t)src * 128 + base2;
                    float2 h0 = unpack2(hh2[rb]);
                    float2 h1 = unpack2(hh2[rb + 4]);
                    float2 h2 = unpack2(hh2[rb + 2]);
                    float2 h3 = unpack2(hh2[rb + 6]);
                    float hr[8] = {h0.x,h0.y,h1.x,h1.y,h2.x,h2.y,h3.x,h3.y};
                    #pragma unroll
                    for (int j = 0; j < 8; j++) {
                        float m = hr[j] + ebr[j]
                                + ea0 * wj[j][0] + ea1 * wj[j][1] + ea2 * wj[j][2]
                                + ea3 * wj[j][3] + ea4 * wj[j][4];
                        acc[j] += fmaxf(m, 0.f);
                    }
                }
                size_t nb = (size_t)node * 128 + base2;
                float2 v0 = unpack2(hh2[nb]),     v1 = unpack2(hh2[nb + 4]);
                float2 v2 = unpack2(hh2[nb + 2]), v3 = unpack2(hh2[nb + 6]);
                rv[0]=v0.x+acc[0]; rv[1]=v0.y+acc[1]; rv[2]=v1.x+acc[2]; rv[3]=v1.y+acc[3];
                rv[4]=v2.x+acc[4]; rv[5]=v2.y+acc[5]; rv[6]=v3.x+acc[6]; rv[7]=v3.y+acc[7];
            }
            int ubase = ((i * 16 + S) * 2 + hloc) * 32;
            smA[ubase + gloc * 4 + t0]     = make_uint2(pack2(rv[0], rv[1]), pack2(rv[2], rv[3]));
            smA[ubase + gloc * 4 + t0 + 2] = make_uint2(pack2(rv[4], rv[5]), pack2(rv[6], rv[7]));
        }
    }
    __syncthreads();   // A complete

    float acc[4][4][4];

    // ================= stage 1: z1 = relu(A@W1 + b1) =================
    #pragma unroll
    for (int i = 0; i < 4; i++)
        #pragma unroll
        for (int j = 0; j < 4; j++) {
            acc[i][j][0]=0.f; acc[i][j][1]=0.f; acc[i][j][2]=0.f; acc[i][j][3]=0.f;
        }

    for (int st = 0; st < 8; st++) {
        int buf = st & 1;
        if (st + 1 < 8) {
            load_B(buf ^ 1, st + 1, W1f);
            asm volatile("cp.async.commit_group;");
            asm volatile("cp.async.wait_group 1;");
        } else {
            asm volatile("cp.async.wait_group 0;");
        }
        __syncthreads();
        const uint2* sB2 = (const uint2*)(smB + buf * 16384);
        #pragma unroll
        for (int Sl = 0; Sl < 2; Sl++) {
            int S = st * 2 + Sl;
            unsigned af[4][4];
            unsigned bf[4][2];
            #pragma unroll
            for (int mt = 0; mt < 4; mt++) {
                int mtIdx = warpRow * 4 + mt;
                uint2 u0 = smA[((mtIdx * 16 + S) * 2 + 0) * 32 + lane];
                uint2 u1 = smA[((mtIdx * 16 + S) * 2 + 1) * 32 + lane];
                af[mt][0] = u0.x; af[mt][1] = u1.x; af[mt][2] = u0.y; af[mt][3] = u1.y;
            }
            #pragma unroll
            for (int nt = 0; nt < 4; nt++) {
                uint2 ub = sB2[(wc * 4 + nt) * 64 + Sl * 32 + lane];
                bf[nt][0] = ub.x; bf[nt][1] = ub.y;
            }
            #pragma unroll
            for (int mt = 0; mt < 4; mt++)
                #pragma unroll
                for (int nt = 0; nt < 4; nt++) {
                    asm volatile(
                        "mma.sync.aligned.m16n8k16.row.col.f32.f16.f16.f32 "
                        "{%0,%1,%2,%3}, {%4,%5,%6,%7}, {%8,%9}, {%0,%1,%2,%3};\n"
                        : "+f"(acc[mt][nt][0]), "+f"(acc[mt][nt][1]),
                          "+f"(acc[mt][nt][2]), "+f"(acc[mt][nt][3])
                        : "r"(af[mt][0]), "r"(af[mt][1]), "r"(af[mt][2]), "r"(af[mt][3]),
                          "r"(bf[nt][0]), "r"(bf[nt][1]));
                }
        }
        __syncthreads();
    }

    // prefetch W2 stage 0 (overlaps z1 epilogue)
    load_B(0, 0, W2f);
    asm volatile("cp.async.commit_group;");

    // stage-1 epilogue: relu + b1 -> z1 smem fp16 frags
    #pragma unroll
    for (int mt = 0; mt < 4; mt++) {
        int Rl = warpRow * 4 + mt;
        #pragma unroll
        for (int j = 0; j < 2; j++) {
            int S = wc * 2 + j;
            int ntA = 2 * j, ntB = 2 * j + 1;
            int cA = wc * 32 + ntA * 8 + 2 * t;
            int cB = cA + 8;
            float bA0 = b1[cA], bA1 = b1[cA + 1];
            float bB0 = b1[cB], bB1 = b1[cB + 1];
            float a0 = fmaxf(acc[mt][ntA][0] + bA0, 0.f);
            float a1 = fmaxf(acc[mt][ntA][1] + bA1, 0.f);
            float a2 = fmaxf(acc[mt][ntA][2] + bA0, 0.f);
            float a3 = fmaxf(acc[mt][ntA][3] + bA1, 0.f);
            float b0v = fmaxf(acc[mt][ntB][0] + bB0, 0.f);
            float b1v = fmaxf(acc[mt][ntB][1] + bB1, 0.f);
            float b2v = fmaxf(acc[mt][ntB][2] + bB0, 0.f);
            float b3v = fmaxf(acc[mt][ntB][3] + bB1, 0.f);
            int ubase = ((Rl * 16 + S) * 2) * 32;
            smZ[ubase + lane]      = make_uint2(pack2(a0, a1), pack2(b0v, b1v));
            smZ[ubase + 32 + lane] = make_uint2(pack2(a2, a3), pack2(b2v, b3v));
        }
    }

    // ================= stage 2: z2 = z1 @ W2 + b2 =================
    #pragma unroll
    for (int i = 0; i < 4; i++)
        #pragma unroll
        for (int j = 0; j < 4; j++) {
            acc[i][j][0]=0.f; acc[i][j][1]=0.f; acc[i][j][2]=0.f; acc[i][j][3]=0.f;
        }
    __syncthreads();   // z1 visible

    for (int st = 0; st < 8; st++) {
        int buf = st & 1;
        if (st + 1 < 8) {
            load_B(buf ^ 1, st + 1, W2f);
            asm volatile("cp.async.commit_group;");
            asm volatile("cp.async.wait_group 1;");
        } else {
            asm volatile("cp.async.wait_group 0;");
        }
        __syncthreads();
        const uint2* sB2 = (const uint2*)(smB + buf * 16384);
        #pragma unroll
        for (int Sl = 0; Sl < 2; Sl++) {
            int S = st * 2 + Sl;
            unsigned af[4][4];
            unsigned bf[4][2];
            #pragma unroll
            for (int mt = 0; mt < 4; mt++) {
                int mtIdx = warpRow * 4 + mt;
                uint2 u0 = smZ[((mtIdx * 16 + S) * 2 + 0) * 32 + lane];
                uint2 u1 = smZ[((mtIdx * 16 + S) * 2 + 1) * 32 + lane];
                af[mt][0] = u0.x; af[mt][1] = u1.x; af[mt][2] = u0.y; af[mt][3] = u1.y;
            }
            #pragma unroll
            for (int nt = 0; nt < 4; nt++) {
                uint2 ub = sB2[(wc * 4 + nt) * 64 + Sl * 32 + lane];
                bf[nt][0] = ub.x; bf[nt][1] = ub.y;
            }
            #pragma unroll
            for (int mt = 0; mt < 4; mt++)
                #pragma unroll
                for (int nt = 0; nt < 4; nt++) {
                    asm volatile(
                        "mma.sync.aligned.m16n8k16.row.col.f32.f16.f16.f32 "
                        "{%0,%1,%2,%3}, {%4,%5,%6,%7}, {%8,%9}, {%0,%1,%2,%3};\n"
                        : "+f"(acc[mt][nt][0]), "+f"(acc[mt][nt][1]),
                          "+f"(acc[mt][nt][2]), "+f"(acc[mt][nt][3])
                        : "r"(af[mt][0]), "r"(af[mt][1]), "r"(af[mt][2]), "r"(af[mt][3]),
                          "r"(bf[nt][0]), "r"(bf[nt][1]));
                }
        }
        __syncthreads();
    }

    // stage-2 epilogue: fp16 z2 + fused BN sums
    unsigned* Z1 = (unsigned*)Zh;
    #pragma unroll
    for (int nt = 0; nt < 4; nt++) {
        int c0 = wc * 32 + nt * 8 + 2 * t;
        float b0 = b2[c0], b1v = b2[c0 + 1];
        float s0 = 0.f, q0 = 0.f, s1 = 0.f, q1 = 0.f;
        #pragma unroll
        for (int mt = 0; mt < 4; mt++) {
            int r0 = bm + warpRow * 64 + mt * 16 + g;
            int r1 = r0 + 8;
            float v0 = acc[mt][nt][0] + b0;
            float v1 = acc[mt][nt][1] + b1v;
            float v2 = acc[mt][nt][2] + b0;
            float v3 = acc[mt][nt][3] + b1v;
            if (r0 < NN) {
                Z1[((size_t)r0 * HID + c0) >> 1] = pack2(v0, v1);
                s0 += v0; q0 += v0 * v0; s1 += v1; q1 += v1 * v1;
            }
            if (r1 < NN) {
                Z1[((size_t)r1 * HID + c0) >> 1] = pack2(v2, v3);
                s0 += v2; q0 += v2 * v2; s1 += v3; q1 += v3 * v3;
            }
        }
        #pragma unroll
        for (int off = 16; off >= 4; off >>= 1) {
            s0 += __shfl_down_sync(FULL, s0, off);
            q0 += __shfl_down_sync(FULL, q0, off);
            s1 += __shfl_down_sync(FULL, s1, off);
            q1 += __shfl_down_sync(FULL, q1, off);
        }
        if (lane < 4) {
            atomicAdd(&bnsum[c0],           s0);
            atomicAdd(&bnsum[c0 + 1],       s1);
            atomicAdd(&bnsum[HID + c0],     q0);
            atomicAdd(&bnsum[HID + c0 + 1], q1);
        }
    }
}

// ---------------- fp32 SIMT GEMM (head only) ----------------
template <int RELU>
__global__ void k_gemm(const float* __restrict__ A, const float* __restrict__ B,
                       const float* __restrict__ bias, float* __restrict__ C,
                       int M, int N, int K) {
    __shared__ float As[16][64];
    __shared__ float Bs[16][64];
    int tid = threadIdx.x;
    int tx = tid & 15, ty = tid >> 4;
    int bm = blockIdx.x * 64, bn = blockIdx.y * 64;
    int aR = tid >> 2;
    int aC = (tid & 3) * 4;
    int bR = tid >> 4;
    int bC = (tid & 15) * 4;
    int gArow = bm + aR;
    float acc[4][4] = {};
    for (int k0 = 0; k0 < K; k0 += 16) {
        float4 av = (gArow < M) ? *(const float4*)(A + (size_t)gArow * K + k0 + aC)
                                : make_float4(0.f, 0.f, 0.f, 0.f);
        As[aC + 0][aR] = av.x;
        As[aC + 1][aR] = av.y;
        As[aC + 2][aR] = av.z;
        As[aC + 3][aR] = av.w;
        *(float4*)&Bs[bR][bC] = *(const float4*)(B + (size_t)(k0 + bR) * N + bn + bC);
        __syncthreads();
        #pragma unroll
        for (int k = 0; k < 16; k++) {
            float4 a4 = *(const float4*)&As[k][ty * 4];
            float4 b4 = *(const float4*)&Bs[k][tx * 4];
            float ar[4] = {a4.x, a4.y, a4.z, a4.w};
            float br[4] = {b4.x, b4.y, b4.z, b4.w};
            #pragma unroll
            for (int i = 0; i < 4; i++)
                #pragma unroll
                for (int j = 0; j < 4; j++)
                    acc[i][j] += ar[i] * br[j];
        }
        __syncthreads();
    }
    #pragma unroll
    for (int i = 0; i < 4; i++) {
        int r = bm + ty * 4 + i;
        if (r < M) {
            #pragma unroll
            for (int j = 0; j < 4; j++) {
                int c = bn + tx * 4 + j;
                float v = acc[i][j] + bias[c];
                if (RELU) v = fmaxf(v, 0.f);
                C[(size_t)r * N + c] = v;
            }
        }
    }
}

// ---------------- batchnorm apply with fused fin ----------------
__global__ void k_bn_apply(const float* __restrict__ bnsum,
                           const float* __restrict__ gamma,
                           const float* __restrict__ beta) {
    __shared__ float smSc[HID], smSh[HID];
    int tid = threadIdx.x;   // 512
    if (tid < HID) {
        float mu = bnsum[tid] * (1.f / NN);
        float var = bnsum[HID + tid] * (1.f / NN) - mu * mu;
        float inv = rsqrtf(var + BN_EPS);
        float sc = inv * gamma[tid];
        smSc[tid] = sc;
        smSh[tid] = beta[tid] - mu * sc;
    }
    __syncthreads();
    int idx = blockIdx.x * blockDim.x + tid;   // 4-channel unit
    if (idx < NN * 64) {
        int c4 = idx & 63;
        uint2 zu = ((const uint2*)g_z2h)[idx];
        float2 z01 = unpack2(zu.x);
        float2 z23 = unpack2(zu.y);
        float4 sc = ((const float4*)smSc)[c4];
        float4 sh = ((const float4*)smSh)[c4];
        uint2 hu = ((const uint2*)g_hh)[idx];
        float2 h01 = unpack2(hu.x);
        float2 h23 = unpack2(hu.y);
        float r0 = fmaxf(z01.x * sc.x + sh.x, 0.f) + h01.x;
        float r1 = fmaxf(z01.y * sc.y + sh.y, 0.f) + h01.y;
        float r2 = fmaxf(z23.x * sc.z + sh.z, 0.f) + h23.x;
        float r3 = fmaxf(z23.y * sc.w + sh.w, 0.f) + h23.y;
        ((uint2*)g_hh)[idx] = make_uint2(pack2(r0, r1), pack2(r2, r3));
    }
}

// ---------------- pooling ----------------
__global__ void k_pool(const int* __restrict__ batch) {
    __shared__ int sb[128];
    int c = threadIdx.x;
    int n0 = blockIdx.x * 128;
    int n1 = min(n0 + 128, NN);
    if (c < 128 && n0 + c < NN) sb[c] = batch[n0 + c];
    __syncthreads();
    float accS = 0.f, accM = 0.f;
    int cur = sb[0];
    int cnt = 0;
    for (int n = n0; n < n1; n++) {
        int gg = sb[n - n0];
        if (gg != cur) {
            atomicAdd(&g_psum[cur * HID + c], accS);
            atomicMax((int*)&g_pmax[cur * HID + c], __float_as_int(accM));
            if (c == 0) atomicAdd(&g_cnt[cur], cnt);
            accS = 0.f; accM = 0.f; cnt = 0; cur = gg;
        }
        float v = __half2float(g_hh[(size_t)n * HID + c]);
        accS += v;
        accM = fmaxf(accM, v);
        cnt++;
    }
    atomicAdd(&g_psum[cur * HID + c], accS);
    atomicMax((int*)&g_pmax[cur * HID + c], __float_as_int(accM));
    if (c == 0) atomicAdd(&g_cnt[cur], cnt);
}

__global__ void k_pool_fin() {
    int g = blockIdx.x, c = threadIdx.x;
    float s = g_psum[g * HID + c];
    float cnt = (float)max(g_cnt[g], 1);
    g_gfeat[g * 3 * HID + c]            = s / cnt;
    g_gfeat[g * 3 * HID + HID + c]      = s;
    g_gfeat[g * 3 * HID + 2 * HID + c]  = g_pmax[g * HID + c];
}

// ---------------- head final ----------------
__global__ void k_final(const float* __restrict__ W3, const float* __restrict__ b3,
                        float* __restrict__ out) {
    __shared__ float red[128];
    int g = blockIdx.x, t = threadIdx.x;
    red[t] = g_h2[g * 128 + t] * W3[t];
    __syncthreads();
    for (int off = 64; off > 0; off >>= 1) {
        if (t < off) red[t] += red[t + off];
        __syncthreads();
    }
    if (t == 0) out[g] = red[0] + b3[0];
}

// ---------------- launch ----------------
extern "C" void kernel_launch(void* const* d_in, const int* in_sizes, int n_in,
                              void* d_out, int out_size) {
    const float* x     = (const float*)d_in[0];
    const int*   ei    = (const int*)  d_in[1];
    const float* eattr = (const float*)d_in[2];
    const int*   batch = (const int*)  d_in[3];
    const float* encW  = (const float*)d_in[4];
    const float* encb  = (const float*)d_in[5];
    const float* edgeW = (const float*)d_in[6];
    const float* edgeb = (const float*)d_in[7];
    const float* W1    = (const float*)d_in[8];
    const float* b1    = (const float*)d_in[9];
    const float* W2    = (const float*)d_in[10];
    const float* b2    = (const float*)d_in[11];
    const float* bng   = (const float*)d_in[12];
    const float* bnb   = (const float*)d_in[13];
    const float* hW1   = (const float*)d_in[14];
    const float* hb1   = (const float*)d_in[15];
    const float* hW2   = (const float*)d_in[16];
    const float* hb2   = (const float*)d_in[17];
    const float* hW3   = (const float*)d_in[18];
    const float* hb3   = (const float*)d_in[19];
    float* out = (float*)d_out;

    float *p_gf, *p_h1, *p_h2, *p_bnsumL;
    __half *p_wf, *p_z2h;
    cudaGetSymbolAddress((void**)&p_gf, g_gfeat);
    cudaGetSymbolAddress((void**)&p_h1, g_h1);
    cudaGetSymbolAddress((void**)&p_h2, g_h2);
    cudaGetSymbolAddress((void**)&p_wf, g_wf);
    cudaGetSymbolAddress((void**)&p_z2h, g_z2h);
    cudaGetSymbolAddress((void**)&p_bnsumL, g_bnsumL);

    cudaFuncSetAttribute(k_layer, cudaFuncAttributeMaxDynamicSharedMemorySize, LYR_SMEM);

    // CSR build + init + weight prep
    k_zero_init<<<512, 256>>>();
    k_hist<<<(NE + 255) / 256, 256>>>(ei);
    k_scan<<<1, 1024>>>();
    k_scatter<<<(NE + 255) / 256, 256>>>(ei, eattr);
    k_wprep<<<8, 256>>>(W1, W2);

    // encoder
    k_enc<<<NN, HID>>>(x, encW, encb);

    for (int l = 0; l < NL; l++) {
        k_layer<<<NNPAD / 128, 512, LYR_SMEM>>>(
            edgeW + (size_t)l * EDIM * HID, edgeb + l * HID,
            p_wf + (size_t)(l * 2 + 0) * HID * HID,
            p_wf + (size_t)(l * 2 + 1) * HID * HID,
            b1 + l * HID, b2 + l * HID, p_z2h,
            p_bnsumL + l * 2 * HID);
        k_bn_apply<<<(NN * 64 + 511) / 512, 512>>>(p_bnsumL + l * 2 * HID,
                                                   bng + l * HID, bnb + l * HID);
    }

    // pooling + head
    k_pool<<<(NN + 127) / 128, 256>>>(batch);
    k_pool_fin<<<NG, HID>>>();
    k_gemm<1><<<dim3(NG / 64, HID / 64), 256>>>(p_gf, hW1, hb1, p_h1, NG, HID, 3 * HID);
    k_gemm<1><<<dim3(NG / 64, (HID / 2) / 64), 256>>>(p_h1, hW2, hb2, p_h2, NG, HID / 2, HID);
    k_final<<<NG, 128>>>(hW3, hb3, out);
}